// round 17
// baseline (speedup 1.0000x reference)
#include <cuda_runtime.h>
#include <cuda_fp16.h>
#include <cstdint>

// Problem constants (fixed-shape problem)
#define BB 4
#define TT 12
#define NN 10000
#define FF 32
#define EE 160000
#define MM (BB*NN)          // 40000 rows
#define SLICES (BB*TT)      // 48
#define SL (NN*FF)          // 320000 elements per slice
#define SL2 (SL/2)          // slice stride in pair units
#define NTASK (MM/16)       // 2500 gru row-groups

typedef unsigned long long ull;

// -------- device scratch (static, no allocation; zero-initialized) --------
__device__ uint32_t d_xh[SLICES * NN * 16];   // x in fp16x2 (30.7MB)
__device__ uint32_t d_XAh[SLICES * NN * 16];  // aggregated features, fp16x2 (30.7MB)
__device__ float d_deg[NN];
__device__ float d_dinv[NN];
__device__ int   d_cnt[NN];
__device__ int   d_fill[NN];
__device__ int   d_rowptr[NN + 1];
__device__ int2  d_csrp[EE];               // packed {src_row, weight_bits}
__device__ float d_bf[96];                 // folded biases z|r|h
__device__ float d_probs[TT];
// mma fragment-ordered f16x2 weights, 2-term (hi/lo): [term][nt][kt][lane][reg]
__device__ uint32_t d_fB1[2 * 12 * 4 * 32 * 2];   // gates B: K=64, N=96
__device__ uint32_t d_fUh[2 * 4 * 2 * 32 * 2];    // Uh:      K=32, N=32
__device__ uint32_t d_fLn[2 * 4 * 2 * 32 * 2];    // lin_w:   K=32, N=32

// ===================== f32x2 helpers =====================
__device__ __forceinline__ void fma2(ull& d, ull a, ull b) {
    asm("fma.rn.f32x2 %0, %1, %2, %0;" : "+l"(d) : "l"(a), "l"(b));
}
__device__ __forceinline__ void mul2(ull& d, ull a, ull b) {
    asm("mul.rn.f32x2 %0, %1, %2;" : "=l"(d) : "l"(a), "l"(b));
}
__device__ __forceinline__ ull splat2(float w) {
    ull r; asm("mov.b64 %0, {%1, %1};" : "=l"(r) : "f"(w)); return r;
}
__device__ __forceinline__ float2 unpk(ull a) {
    float2 f; asm("mov.b64 {%0, %1}, %2;" : "=f"(f.x), "=f"(f.y) : "l"(a)); return f;
}

// ===================== fp16 pack/split helpers =====================
__device__ __forceinline__ uint32_t packh(float a, float b) {
    __half2 h = __floats2half2_rn(a, b);        // x=a (low), y=b (high)
    return *(uint32_t*)&h;
}
__device__ __forceinline__ void splith(float a, float b, uint32_t& hi, uint32_t& lo) {
    hi = packh(a, b);
    __half2 hh = *(__half2*)&hi;
    lo = packh(a - __half2float(hh.x), b - __half2float(hh.y));
}
// half2 bits -> packed f32x2 (ull)
__device__ __forceinline__ ull h2f2(uint32_t h) {
    float2 f = __half22float2(*(__half2*)&h);
    ull r; asm("mov.b64 %0, {%1, %2};" : "=l"(r) : "f"(f.x), "f"(f.y));
    return r;
}
// mma.sync m16n8k16 row.col fp16 -> f32, D += A*B
__device__ __forceinline__ void mma16816(float* d, const uint32_t* a,
                                         uint32_t b0, uint32_t b1) {
    asm("mma.sync.aligned.m16n8k16.row.col.f32.f16.f16.f32 "
        "{%0,%1,%2,%3}, {%4,%5,%6,%7}, {%8,%9}, {%0,%1,%2,%3};"
        : "+f"(d[0]), "+f"(d[1]), "+f"(d[2]), "+f"(d[3])
        : "r"(a[0]), "r"(a[1]), "r"(a[2]), "r"(a[3]), "r"(b0), "r"(b1));
}

// -------- fused: x -> fp16 conversion + degree/count accumulation --------
// 7500 blocks x 256 threads: thread i converts 8 floats (one uint4 store);
// threads with i < EE also accumulate degree counters.
__global__ void __launch_bounds__(256) k_deg_conv(const float* __restrict__ x,
                                                  const int* __restrict__ ei,
                                                  const float* __restrict__ ew) {
    int i = blockIdx.x * blockDim.x + threadIdx.x;
    long o = (long)i * 8;
    if (o < (long)SLICES * SL) {
        float4 f0 = __ldg((const float4*)(x + o));
        float4 f1 = __ldg((const float4*)(x + o + 4));
        uint4 u;
        u.x = packh(f0.x, f0.y); u.y = packh(f0.z, f0.w);
        u.z = packh(f1.x, f1.y); u.w = packh(f1.z, f1.w);
        *(uint4*)(d_xh + o / 2) = u;
    }
    if (i < EE) {
        int col = ei[EE + i];
        atomicAdd(&d_deg[col], ew[i]);
        atomicAdd(&d_cnt[col], 1);
    }
}

// single-block: parallel shared fold + fragment build + dinv + scan +
// bias fold + softmax + counter re-zero.
__global__ void k_scan_prep(const float* att,
                            const float* Wz, const float* bz, const float* lzw, const float* lzb,
                            const float* Wr, const float* br, const float* lrw, const float* lrb,
                            const float* Wh, const float* bh, const float* lhw, const float* lhb,
                            const float* linw) {
    __shared__ float sFold[64 * 96];      // 24KB: B1[k][j] = [W' ; Uz|Ur|0]
    int tid = threadIdx.x;
    int lane = tid & 31;

    {   // ---- parallel fold into shared ----
        int k = tid >> 5, j = tid & 31;
        const float* Ws[3] = {Wz, Wr, Wh};
        const float* ls[3] = {lzw, lrw, lhw};
        #pragma unroll
        for (int g = 0; g < 3; g++) {
            float s = 0.f;
            #pragma unroll
            for (int m = 0; m < 32; m++) s += Ws[g][k * 32 + m] * ls[g][m * 32 + j];
            sFold[k * 96 + g * 32 + j] = s;
        }
        sFold[(32 + k) * 96 +  0 + j] = lzw[(32 + k) * 32 + j];  // Uz
        sFold[(32 + k) * 96 + 32 + j] = lrw[(32 + k) * 32 + j];  // Ur
        sFold[(32 + k) * 96 + 64 + j] = 0.f;
    }
    __syncthreads();

    // ---- B1 fragments (fp16 hi/lo) from shared fold ----
    for (int i = tid; i < 12 * 4 * 32; i += 1024) {
        int nt = i >> 7;
        int kt = (i >> 5) & 3;
        int ln = i & 31;
        int n = nt * 8 + (ln >> 2);
        int kb = kt * 16 + (ln & 3) * 2;
        #pragma unroll
        for (int r = 0; r < 2; r++) {
            int k0 = kb + r * 8;
            float w0 = sFold[k0 * 96 + n];
            float w1 = sFold[(k0 + 1) * 96 + n];
            uint32_t hi, lo;
            splith(w0, w1, hi, lo);
            d_fB1[((0 * 12 + nt) * 4 + kt) * 64 + ln * 2 + r] = hi;
            d_fB1[((1 * 12 + nt) * 4 + kt) * 64 + ln * 2 + r] = lo;
        }
    }
    // ---- Uh + Ln fragments ----
    for (int i = tid; i < 4 * 2 * 32; i += 1024) {
        int nt = i >> 6;
        int kt = (i >> 5) & 1;
        int ln = i & 31;
        int n = nt * 8 + (ln >> 2);
        int kb = kt * 16 + (ln & 3) * 2;
        #pragma unroll
        for (int r = 0; r < 2; r++) {
            int k0 = kb + r * 8;
            float u0 = lhw[(32 + k0) * 32 + n];
            float u1 = lhw[(32 + k0 + 1) * 32 + n];
            float l0 = linw[k0 * 32 + n];
            float l1 = linw[(k0 + 1) * 32 + n];
            uint32_t hi, lo;
            splith(u0, u1, hi, lo);
            d_fUh[((0 * 4 + nt) * 2 + kt) * 64 + ln * 2 + r] = hi;
            d_fUh[((1 * 4 + nt) * 2 + kt) * 64 + ln * 2 + r] = lo;
            splith(l0, l1, hi, lo);
            d_fLn[((0 * 4 + nt) * 2 + kt) * 64 + ln * 2 + r] = hi;
            d_fLn[((1 * 4 + nt) * 2 + kt) * 64 + ln * 2 + r] = lo;
        }
    }
    // ---- folded biases + softmax ----
    if (tid < 96) {
        int g = tid >> 5; int jj = tid & 31;
        const float* bs = (g == 0) ? bz : (g == 1) ? br : bh;
        const float* ls = (g == 0) ? lzw : (g == 1) ? lrw : lhw;
        const float* lb = (g == 0) ? lzb : (g == 1) ? lrb : lhb;
        float s = lb[jj];
        for (int m = 0; m < 32; m++) s += bs[m] * ls[m * 32 + jj];
        d_bf[g * 32 + jj] = s;
    }
    if (tid == 0) {
        float mx = -1e30f;
        for (int i = 0; i < TT; i++) mx = fmaxf(mx, att[i]);
        float e[TT]; float sum = 0.f;
        for (int i = 0; i < TT; i++) { e[i] = expf(att[i] - mx); sum += e[i]; }
        for (int i = 0; i < TT; i++) d_probs[i] = e[i] / sum;
    }

    // ---- dinv ----
    for (int i = tid; i < NN; i += 1024) {
        float d = d_deg[i] + 1.0f;
        d_dinv[i] = rsqrtf(fmaxf(d, 1e-12f));
    }
    // ---- 3-level exclusive scan ----
    __shared__ int warpsum[32];
    int v[10];
    int s = 0;
    int base = tid * 10;
    if (tid < 1000) {
        #pragma unroll
        for (int u = 0; u < 10; u++) { v[u] = s; s += d_cnt[base + u]; }
    }
    int inc = s;
    #pragma unroll
    for (int o = 1; o < 32; o <<= 1) {
        int t = __shfl_up_sync(0xffffffffu, inc, o);
        if (lane >= o) inc += t;
    }
    if (lane == 31) warpsum[tid >> 5] = inc;
    __syncthreads();
    if (tid < 32) {
        int ws = warpsum[tid];
        int winc = ws;
        #pragma unroll
        for (int o = 1; o < 32; o <<= 1) {
            int t = __shfl_up_sync(0xffffffffu, winc, o);
            if (lane >= o) winc += t;
        }
        warpsum[tid] = winc - ws;
    }
    __syncthreads();
    int texcl = warpsum[tid >> 5] + inc - s;
    if (tid < 1000) {
        #pragma unroll
        for (int u = 0; u < 10; u++) d_rowptr[base + u] = texcl + v[u];
    }
    if (tid == 1000) d_rowptr[NN] = texcl;

    __syncthreads();
    for (int i = tid; i < NN; i += 1024) { d_deg[i] = 0.f; d_cnt[i] = 0; d_fill[i] = 0; }
}

__global__ void k_fill(const int* ei, const float* ew) {
    int e = blockIdx.x * blockDim.x + threadIdx.x;
    if (e >= EE) return;
    int r = ei[e];
    int c = ei[EE + e];
    int pos = d_rowptr[c] + atomicAdd(&d_fill[c], 1);
    float w = d_dinv[r] * ew[e] * d_dinv[c];
    d_csrp[pos] = make_int2(r, __float_as_int(w));
}

// -------- aggregation over fp16 x: one warp per (node, 8 slices) ----------
// Lane layout: gq = lane>>3 selects slice within a 4-slice load group,
// f8 = lane&7 selects the 8-byte (4-feature) chunk of the 64B node row.
// Load 1 covers slices g*8+gq, load 2 covers g*8+4+gq: 2 LDG.64 per edge
// (was 4 on fp32 data) -> gather L2 traffic halves to ~492MB.
__global__ void __launch_bounds__(256) k_agg() {
    int w = (blockIdx.x * blockDim.x + threadIdx.x) >> 5;
    int lane = threadIdx.x & 31;
    if (w >= NN * 6) return;
    int g = w / NN;
    int n = w - g * NN;
    int gq = lane >> 3;
    int f8 = lane & 7;

    const ull* px = (const ull*)d_xh;
    int s1 = g * 8 + gq;
    long o1 = (long)s1 * (NN * 8) + f8;         // row = 8 ull
    long o2 = o1 + (long)4 * NN * 8;

    float dn = d_dinv[n];
    ull selfw2 = splat2(dn * dn);
    ull a10, a11, a20, a21;
    {
        int r8 = n * 8;
        ull v1 = __ldg(px + o1 + r8);
        ull v2 = __ldg(px + o2 + r8);
        mul2(a10, h2f2((uint32_t)v1), selfw2);
        mul2(a11, h2f2((uint32_t)(v1 >> 32)), selfw2);
        mul2(a20, h2f2((uint32_t)v2), selfw2);
        mul2(a21, h2f2((uint32_t)(v2 >> 32)), selfw2);
    }
    int e0 = d_rowptr[n], e1 = d_rowptr[n + 1];
    int2 ed;
    if (e0 < e1) ed = __ldg(&d_csrp[e0]);
    for (int e = e0; e < e1; e++) {
        int2 edn;
        if (e + 1 < e1) edn = __ldg(&d_csrp[e + 1]);
        ull w2 = splat2(__int_as_float(ed.y));
        int r8 = ed.x * 8;
        ull v1 = __ldg(px + o1 + r8);
        ull v2 = __ldg(px + o2 + r8);
        fma2(a10, h2f2((uint32_t)v1), w2);
        fma2(a11, h2f2((uint32_t)(v1 >> 32)), w2);
        fma2(a20, h2f2((uint32_t)v2), w2);
        fma2(a21, h2f2((uint32_t)(v2 >> 32)), w2);
        ed = edn;
    }
    // stores: pack back to fp16x2; lane covers pair indices 2*f8, 2*f8+1
    float2 f0 = unpk(a10), f1 = unpk(a11), f2 = unpk(a20), f3 = unpk(a21);
    ull st1 = (ull)packh(f0.x, f0.y) | ((ull)packh(f1.x, f1.y) << 32);
    ull st2 = (ull)packh(f2.x, f2.y) | ((ull)packh(f3.x, f3.y) << 32);
    long so1 = (long)s1 * SL2 + n * 16 + 2 * f8;
    __stcs((ull*)(d_XAh + so1), st1);
    __stcs((ull*)(d_XAh + so1 + (long)4 * SL2), st2);
}

// ==================== warp-MMA GRU (fp16) — unchanged ====================
__global__ void __launch_bounds__(128)
k_gruw(const float* __restrict__ linb, float* __restrict__ out) {
    __shared__ uint32_t sB1[6144];
    __shared__ uint32_t sUh[1024];
    __shared__ uint32_t sLn[1024];
    __shared__ float sbias[96];
    __shared__ float sprob[16];

    int tid = threadIdx.x;
    for (int i = tid; i < 6144; i += 128) sB1[i] = d_fB1[i];
    for (int i = tid; i < 1024; i += 128) { sUh[i] = d_fUh[i]; sLn[i] = d_fLn[i]; }
    if (tid < 96) sbias[tid] = d_bf[tid];
    if (tid < TT) sprob[tid] = d_probs[tid];
    __syncthreads();

    int lane = tid & 31;
    int wid = tid >> 5;
    int task = blockIdx.x * 4 + wid;
    if (task >= NTASK) return;
    int m0 = task * 16;
    int b = m0 / NN;
    long basep = (long)b * (TT * SL2) + (long)(m0 - b * NN) * 16;
    int r1 = lane >> 2;
    int c0q = lane & 3;
    const uint32_t* xr1 = d_XAh + basep + (long)r1 * 16 + c0q;
    const uint32_t* xr2 = xr1 + 8 * 16;
    int c0 = c0q * 2;

    float bias0[12], bias1[12];
    #pragma unroll
    for (int nt = 0; nt < 12; nt++) {
        bias0[nt] = sbias[8 * nt + c0];
        bias1[nt] = sbias[8 * nt + c0 + 1];
    }

    float h[16], hacc[16];
    #pragma unroll
    for (int j = 0; j < 16; j++) { h[j] = 0.f; hacc[j] = 0.f; }

    for (int t = 0; t < TT; t++) {
        uint32_t a[4][4];
        #pragma unroll
        for (int kt = 0; kt < 2; kt++) {
            a[kt][0] = __ldg(xr1 + (long)t * SL2 + 4 * (2 * kt));
            a[kt][1] = __ldg(xr2 + (long)t * SL2 + 4 * (2 * kt));
            a[kt][2] = __ldg(xr1 + (long)t * SL2 + 4 * (2 * kt + 1));
            a[kt][3] = __ldg(xr2 + (long)t * SL2 + 4 * (2 * kt + 1));
        }
        #pragma unroll
        for (int kt = 2; kt < 4; kt++) {
            int hn = 2 * (kt - 2);
            a[kt][0] = packh(h[hn * 4 + 0],       h[hn * 4 + 1]);
            a[kt][1] = packh(h[hn * 4 + 2],       h[hn * 4 + 3]);
            a[kt][2] = packh(h[(hn + 1) * 4 + 0], h[(hn + 1) * 4 + 1]);
            a[kt][3] = packh(h[(hn + 1) * 4 + 2], h[(hn + 1) * 4 + 3]);
        }

        float z[16], hr[16];
        #pragma unroll
        for (int nt = 0; nt < 8; nt++) {
            float d[4];
            d[0] = bias0[nt]; d[1] = bias1[nt]; d[2] = bias0[nt]; d[3] = bias1[nt];
            #pragma unroll
            for (int kt = 0; kt < 4; kt++) {
                uint2 bh = *(const uint2*)&sB1[((0 * 12 + nt) * 4 + kt) * 64 + lane * 2];
                mma16816(d, a[kt], bh.x, bh.y);
            }
            if (nt < 4) {
                #pragma unroll
                for (int i = 0; i < 4; i++)
                    z[nt * 4 + i] = 1.f / (1.f + __expf(-d[i]));
            } else {
                int hn = nt - 4;
                #pragma unroll
                for (int i = 0; i < 4; i++) {
                    float rg = 1.f / (1.f + __expf(-d[i]));
                    hr[hn * 4 + i] = h[hn * 4 + i] * rg;
                }
            }
        }
        uint32_t rfr[2][4];
        #pragma unroll
        for (int kt = 0; kt < 2; kt++) {
            int hn = 2 * kt;
            rfr[kt][0] = packh(hr[hn * 4 + 0],       hr[hn * 4 + 1]);
            rfr[kt][1] = packh(hr[hn * 4 + 2],       hr[hn * 4 + 3]);
            rfr[kt][2] = packh(hr[(hn + 1) * 4 + 0], hr[(hn + 1) * 4 + 1]);
            rfr[kt][3] = packh(hr[(hn + 1) * 4 + 2], hr[(hn + 1) * 4 + 3]);
        }

        float pt = sprob[t];
        #pragma unroll
        for (int nt = 8; nt < 12; nt++) {
            float d[4];
            d[0] = bias0[nt]; d[1] = bias1[nt]; d[2] = bias0[nt]; d[3] = bias1[nt];
            #pragma unroll
            for (int kt = 0; kt < 2; kt++) {
                uint2 bh = *(const uint2*)&sB1[((0 * 12 + nt) * 4 + kt) * 64 + lane * 2];
                mma16816(d, a[kt], bh.x, bh.y);
            }
            int un = nt - 8;
            #pragma unroll
            for (int kt = 0; kt < 2; kt++) {
                uint2 bh = *(const uint2*)&sUh[((0 * 4 + un) * 2 + kt) * 64 + lane * 2];
                mma16816(d, rfr[kt], bh.x, bh.y);
            }
            #pragma unroll
            for (int i = 0; i < 4; i++) {
                int j = un * 4 + i;
                float ht = 2.f / (1.f + __expf(-2.f * d[i])) - 1.f;
                h[j] = z[j] * h[j] + (1.f - z[j]) * ht;
                hacc[j] += pt * h[j];
            }
        }
    }

    uint32_t rfr[2][4];
    #pragma unroll
    for (int kt = 0; kt < 2; kt++) {
        int hn = 2 * kt;
        rfr[kt][0] = packh(fmaxf(hacc[hn * 4 + 0], 0.f),       fmaxf(hacc[hn * 4 + 1], 0.f));
        rfr[kt][1] = packh(fmaxf(hacc[hn * 4 + 2], 0.f),       fmaxf(hacc[hn * 4 + 3], 0.f));
        rfr[kt][2] = packh(fmaxf(hacc[(hn + 1) * 4 + 0], 0.f), fmaxf(hacc[(hn + 1) * 4 + 1], 0.f));
        rfr[kt][3] = packh(fmaxf(hacc[(hn + 1) * 4 + 2], 0.f), fmaxf(hacc[(hn + 1) * 4 + 3], 0.f));
    }
    #pragma unroll
    for (int nt = 0; nt < 4; nt++) {
        float d[4];
        float lb0 = __ldg(&linb[8 * nt + c0]);
        float lb1 = __ldg(&linb[8 * nt + c0 + 1]);
        d[0] = lb0; d[1] = lb1; d[2] = lb0; d[3] = lb1;
        #pragma unroll
        for (int kt = 0; kt < 2; kt++) {
            uint2 bh = *(const uint2*)&sLn[((0 * 4 + nt) * 2 + kt) * 64 + lane * 2];
            uint2 bl = *(const uint2*)&sLn[((1 * 4 + nt) * 2 + kt) * 64 + lane * 2];
            mma16816(d, rfr[kt], bh.x, bh.y);
            mma16816(d, rfr[kt], bl.x, bl.y);
        }
        *(float2*)(out + (long)(m0 + r1) * 32 + 8 * nt + c0)     = make_float2(d[0], d[1]);
        *(float2*)(out + (long)(m0 + r1 + 8) * 32 + 8 * nt + c0) = make_float2(d[2], d[3]);
    }
}

extern "C" void kernel_launch(void* const* d_in, const int* in_sizes, int n_in,
                              void* d_out, int out_size) {
    const float* x  = (const float*)d_in[0];
    const int*   ei = (const int*)d_in[1];
    const float* ew = (const float*)d_in[2];

    int iWz, iBz, iLzw, iLzb, iWr, iBr, iLrw, iLrb, iWh, iBh, iLhw, iLhb;
    if (in_sizes[5] == 2048) {
        iWz = 3; iBz = 4; iLzw = 5;  iLzb = 6;
        iWr = 7; iBr = 8; iLrw = 9;  iLrb = 10;
        iWh = 11; iBh = 12; iLhw = 13; iLhb = 14;
    } else {
        iWz = 3; iBz = 4; iWr = 5; iBr = 6; iWh = 7; iBh = 8;
        iLzw = 9; iLzb = 10; iLrw = 11; iLrb = 12; iLhw = 13; iLhb = 14;
    }
    const float* Wz  = (const float*)d_in[iWz];
    const float* bz  = (const float*)d_in[iBz];
    const float* lzw = (const float*)d_in[iLzw];
    const float* lzb = (const float*)d_in[iLzb];
    const float* Wr  = (const float*)d_in[iWr];
    const float* br  = (const float*)d_in[iBr];
    const float* lrw = (const float*)d_in[iLrw];
    const float* lrb = (const float*)d_in[iLrb];
    const float* Wh  = (const float*)d_in[iWh];
    const float* bh  = (const float*)d_in[iBh];
    const float* lhw = (const float*)d_in[iLhw];
    const float* lhb = (const float*)d_in[iLhb];
    const float* att  = (const float*)d_in[15];
    const float* linw = (const float*)d_in[16];
    const float* linb = (const float*)d_in[17];
    float* out = (float*)d_out;

    // 1: x->fp16 conversion fused with degree counting (7500 blocks)
    k_deg_conv<<<7500, 256>>>(x, ei, ew);
    // 2: fold + fragments + scan + dinv
    k_scan_prep<<<1, 1024>>>(att, Wz, bz, lzw, lzb, Wr, br, lrw, lrb,
                             Wh, bh, lhw, lhb, linw);
    // 3: CSR fill
    k_fill<<<(EE + 255) / 256, 256>>>(ei, ew);
    // 4: aggregation over fp16 x (ncu captures this one)
    {
        int threads = NN * 6 * 32;
        k_agg<<<(threads + 255) / 256, 256>>>();
    }
    // 5: gru
    k_gruw<<<740, 128>>>(linb, out);

    (void)n_in; (void)out_size;
}